// round 10
// baseline (speedup 1.0000x reference)
#include <cuda_runtime.h>
#include <cuda_bf16.h>
#include <cuda_fp16.h>
#include <math.h>

#define NB 4
#define NN 4096
#define CC 64
#define SHIFT 40.0f

// Scratch (device globals — no allocation allowed)
__device__ __half g_Qh[NB * NN * CC];                // fp16 Q
__device__ __half g_Kh[NB * NN * CC];                // fp16 K
__device__ float g_V[NB * NN * CC];                  // full fp32
__device__ __nv_bfloat16 g_Vsb[NB * NN * CC];        // bf16(V * R)
__device__ __nv_bfloat16 g_P[(size_t)NB * NN * NN];  // unnormalized exp(E - SHIFT)
__device__ float g_Sp[NB * 32 * NN];                 // partial row sums per n-tile

// ---------------------------------------------------------------------------
// helpers
// ---------------------------------------------------------------------------
__device__ __forceinline__ void mma_fp16(float& c0, float& c1, float& c2, float& c3,
                                         unsigned a0, unsigned a1, unsigned a2, unsigned a3,
                                         unsigned b0, unsigned b1) {
  asm volatile(
      "mma.sync.aligned.m16n8k16.row.col.f32.f16.f16.f32 "
      "{%0,%1,%2,%3},{%4,%5,%6,%7},{%8,%9},{%0,%1,%2,%3};"
      : "+f"(c0), "+f"(c1), "+f"(c2), "+f"(c3)
      : "r"(a0), "r"(a1), "r"(a2), "r"(a3), "r"(b0), "r"(b1));
}

__device__ __forceinline__ void mma_bf16(float& c0, float& c1, float& c2, float& c3,
                                         unsigned a0, unsigned a1, unsigned a2, unsigned a3,
                                         unsigned b0, unsigned b1) {
  asm volatile(
      "mma.sync.aligned.m16n8k16.row.col.f32.bf16.bf16.f32 "
      "{%0,%1,%2,%3},{%4,%5,%6,%7},{%8,%9},{%0,%1,%2,%3};"
      : "+f"(c0), "+f"(c1), "+f"(c2), "+f"(c3)
      : "r"(a0), "r"(a1), "r"(a2), "r"(a3), "r"(b0), "r"(b1));
}

__device__ __forceinline__ void ldsm4(unsigned& r0, unsigned& r1, unsigned& r2,
                                      unsigned& r3, const void* p) {
  unsigned addr = (unsigned)__cvta_generic_to_shared(p);
  asm volatile(
      "ldmatrix.sync.aligned.m8n8.x4.shared.b16 {%0,%1,%2,%3}, [%4];"
      : "=r"(r0), "=r"(r1), "=r"(r2), "=r"(r3)
      : "r"(addr));
}

__device__ __forceinline__ void ldsm4t(unsigned& r0, unsigned& r1, unsigned& r2,
                                       unsigned& r3, const void* p) {
  unsigned addr = (unsigned)__cvta_generic_to_shared(p);
  asm volatile(
      "ldmatrix.sync.aligned.m8n8.x4.trans.shared.b16 {%0,%1,%2,%3}, [%4];"
      : "=r"(r0), "=r"(r1), "=r"(r2), "=r"(r3)
      : "r"(addr));
}

__device__ __forceinline__ void cp16(void* smem_dst, const void* gsrc) {
  unsigned dst = (unsigned)__cvta_generic_to_shared(smem_dst);
  asm volatile("cp.async.cg.shared.global [%0], [%1], 16;" ::"r"(dst), "l"(gsrc)
               : "memory");
}

// ---------------------------------------------------------------------------
// Kernel 1: fused Q/K/V projection, W in smem. 64 rows/block.
// ---------------------------------------------------------------------------
__global__ __launch_bounds__(256) void qkv_kernel(
    const float* __restrict__ x,
    const float* __restrict__ Wq, const float* __restrict__ bq,
    const float* __restrict__ Wk, const float* __restrict__ bk,
    const float* __restrict__ Wv, const float* __restrict__ bv) {
  extern __shared__ float qsm[];
  float* xs = qsm;            // [64][65]
  float* ws = qsm + 64 * 65;  // [3][64][65]

  const int tid = threadIdx.x;
  const int row0 = blockIdx.x * 64;

  #pragma unroll
  for (int i = tid; i < 64 * 64; i += 256) {
    int r = i >> 6, c = i & 63;
    xs[r * 65 + c] = x[(size_t)(row0 + r) * 64 + c];
  }
  #pragma unroll
  for (int i = tid; i < 3 * 64 * 64; i += 256) {
    int mat = i >> 12, rem = i & 4095;
    int c = rem >> 6, f = rem & 63;
    const float* W = (mat == 0) ? Wq : (mat == 1) ? Wk : Wv;
    ws[(mat * 64 + c) * 65 + f] = W[c * 64 + f];
  }
  __syncthreads();

  const int lane = tid & 31;
  const int w = tid >> 5;
  const int f0 = lane, f1 = lane + 32;

  float aq[2][8], ak[2][8], av[2][8];
  {
    float bq0 = bq[f0], bq1 = bq[f1];
    float bk0 = bk[f0], bk1 = bk[f1];
    float bv0 = bv[f0], bv1 = bv[f1];
    #pragma unroll
    for (int i = 0; i < 8; i++) {
      aq[0][i] = bq0; aq[1][i] = bq1;
      ak[0][i] = bk0; ak[1][i] = bk1;
      av[0][i] = bv0; av[1][i] = bv1;
    }
  }

  #pragma unroll 4
  for (int c = 0; c < 64; c++) {
    float wq0 = ws[(0 * 64 + c) * 65 + f0], wq1 = ws[(0 * 64 + c) * 65 + f1];
    float wk0 = ws[(1 * 64 + c) * 65 + f0], wk1 = ws[(1 * 64 + c) * 65 + f1];
    float wv0 = ws[(2 * 64 + c) * 65 + f0], wv1 = ws[(2 * 64 + c) * 65 + f1];
    #pragma unroll
    for (int i = 0; i < 8; i++) {
      float xv = xs[(w * 8 + i) * 65 + c];
      aq[0][i] += xv * wq0; aq[1][i] += xv * wq1;
      ak[0][i] += xv * wk0; ak[1][i] += xv * wk1;
      av[0][i] += xv * wv0; av[1][i] += xv * wv1;
    }
  }

  #pragma unroll
  for (int i = 0; i < 8; i++) {
    size_t base = (size_t)(row0 + w * 8 + i) * 64;
    g_Qh[base + f0] = __float2half_rn(aq[0][i]);
    g_Qh[base + f1] = __float2half_rn(aq[1][i]);
    g_Kh[base + f0] = __float2half_rn(ak[0][i]);
    g_Kh[base + f1] = __float2half_rn(ak[1][i]);
    g_V[base + f0] = av[0][i];
    g_V[base + f1] = av[1][i];
  }
}

// ---------------------------------------------------------------------------
// Pass 1: E tile (128m x 128n) via fp16 m16n8k16 MMA + ldmatrix;
// P = exp(E - SHIFT) -> bf16 to HBM; per-row partial sums -> g_Sp.
// ---------------------------------------------------------------------------
__global__ __launch_bounds__(256, 2) void pass1_kernel() {
  extern __shared__ char sm1[];
  __half* qh = (__half*)sm1;                       // [128][72]
  __half* kh = (__half*)(sm1 + 128 * 72 * 2);      // [128][72]
  float* ssum = (float*)(sm1 + 2 * 128 * 72 * 2);  // [128]
  __nv_bfloat162* ps2 = (__nv_bfloat162*)sm1;      // overlay [128][68]

  const int b = blockIdx.z;
  const int m0 = blockIdx.y * 128;
  const int n0 = blockIdx.x * 128;
  const int tid = threadIdx.x;
  const __half* Qb = g_Qh + (size_t)b * NN * CC;
  const __half* Kb = g_Kh + (size_t)b * NN * CC;

  #pragma unroll
  for (int i = tid; i < 1024; i += 256) {
    int r = i >> 3, s = i & 7;
    cp16(&qh[r * 72 + s * 8], Qb + (size_t)(m0 + r) * 64 + s * 8);
    cp16(&kh[r * 72 + s * 8], Kb + (size_t)(n0 + r) * 64 + s * 8);
  }
  asm volatile("cp.async.commit_group;" ::: "memory");
  if (tid < 128) ssum[tid] = 0.0f;
  asm volatile("cp.async.wait_group 0;" ::: "memory");
  __syncthreads();

  const int lane = tid & 31;
  const int wid = tid >> 5;
  const int gid = lane >> 2, tig = lane & 3;
  const int mw = (wid >> 1) * 32;
  const int nw = (wid & 1) * 64;

  const int lq = lane & 7;
  const int lsel = lane >> 3;
  const int row_off = lq + ((lsel & 1) ? 8 : 0);
  const int col_off = (lsel & 2) ? 8 : 0;

  float acc[2][8][4];
  #pragma unroll
  for (int t = 0; t < 2; t++)
    #pragma unroll
    for (int j = 0; j < 8; j++)
      #pragma unroll
      for (int c = 0; c < 4; c++) acc[t][j][c] = 0.0f;

  #pragma unroll
  for (int k0 = 0; k0 < 64; k0 += 16) {
    unsigned a[2][4];
    #pragma unroll
    for (int t = 0; t < 2; t++)
      ldsm4(a[t][0], a[t][1], a[t][2], a[t][3],
            &qh[(mw + t * 16 + row_off) * 72 + k0 + col_off]);

    unsigned bf[8][2];
    #pragma unroll
    for (int j2 = 0; j2 < 4; j2++) {
      unsigned r0, r1, r2, r3;
      ldsm4(r0, r1, r2, r3, &kh[(nw + j2 * 16 + row_off) * 72 + k0 + col_off]);
      bf[2 * j2][0] = r0; bf[2 * j2 + 1][0] = r1;
      bf[2 * j2][1] = r2; bf[2 * j2 + 1][1] = r3;
    }

    #pragma unroll
    for (int t = 0; t < 2; t++)
      #pragma unroll
      for (int j = 0; j < 8; j++)
        mma_fp16(acc[t][j][0], acc[t][j][1], acc[t][j][2], acc[t][j][3],
                 a[t][0], a[t][1], a[t][2], a[t][3], bf[j][0], bf[j][1]);
  }

  __syncthreads();  // tile reads done; safe to overlay ps2

  #pragma unroll
  for (int t = 0; t < 2; t++) {
    float s0 = 0.0f, s1 = 0.0f;
    int r0 = mw + t * 16 + gid;
    #pragma unroll
    for (int j = 0; j < 8; j++) {
      float e0 = __expf(acc[t][j][0] - SHIFT);
      float e1 = __expf(acc[t][j][1] - SHIFT);
      float e2 = __expf(acc[t][j][2] - SHIFT);
      float e3 = __expf(acc[t][j][3] - SHIFT);
      s0 += e0 + e1;
      s1 += e2 + e3;
      int cp = (nw >> 1) + j * 4 + tig;
      ps2[r0 * 68 + cp] = __floats2bfloat162_rn(e0, e1);
      ps2[(r0 + 8) * 68 + cp] = __floats2bfloat162_rn(e2, e3);
    }
    s0 += __shfl_xor_sync(0xffffffffu, s0, 1);
    s0 += __shfl_xor_sync(0xffffffffu, s0, 2);
    s1 += __shfl_xor_sync(0xffffffffu, s1, 1);
    s1 += __shfl_xor_sync(0xffffffffu, s1, 2);
    if (tig == 0) {
      atomicAdd(&ssum[r0], s0);
      atomicAdd(&ssum[r0 + 8], s1);
    }
  }
  __syncthreads();

  if (tid < 128)
    g_Sp[((size_t)b * 32 + blockIdx.x) * NN + m0 + tid] = ssum[tid];

  __nv_bfloat162* GP = (__nv_bfloat162*)(g_P + (size_t)b * NN * NN);
  #pragma unroll
  for (int i = tid; i < 128 * 64; i += 256) {
    int r = i >> 6, c = i & 63;
    GP[(size_t)(m0 + r) * (NN / 2) + (n0 >> 1) + c] = ps2[r * 68 + c];
  }
}

// ---------------------------------------------------------------------------
// norm: fused rsum + vscale (bf16 out). One warp per row.
// ---------------------------------------------------------------------------
__global__ __launch_bounds__(256) void norm_kernel() {
  const int row = blockIdx.x * 8 + (threadIdx.x >> 5);  // < NB*NN
  const int lane = threadIdx.x & 31;
  const int b = row >> 12, m = row & (NN - 1);

  float s = g_Sp[((size_t)b * 32 + lane) * NN + m];
  #pragma unroll
  for (int off = 16; off; off >>= 1) s += __shfl_xor_sync(0xffffffffu, s, off);
  const float rinv = 1.0f / s;

  size_t base = (size_t)row * 64;
  float v0 = g_V[base + 2 * lane], v1 = g_V[base + 2 * lane + 1];
  *(__nv_bfloat162*)&g_Vsb[base + 2 * lane] =
      __floats2bfloat162_rn(v0 * rinv, v1 * rinv);
}

// ---------------------------------------------------------------------------
// Pass 2: out[n,c] = gamma * sum_m P[m,n]*Vsb[m,c] + x[n,c]
// n-tile 32, grid (128, NB) = 512 blocks; 4-slot cp.async ring (3 in flight).
// 8 warps as 2n x 4c (warp tile 16n x 16c). smem 57344 B, 3 CTAs/SM.
// ---------------------------------------------------------------------------
__global__ __launch_bounds__(256, 3) void pass2_kernel(
    const float* __restrict__ x, const float* __restrict__ gamma,
    float* __restrict__ out) {
  extern __shared__ char sm[];
  __nv_bfloat16* praw = (__nv_bfloat16*)sm;                      // [4][64][40]
  __nv_bfloat16* vraw = (__nv_bfloat16*)(sm + 4 * 64 * 40 * 2);  // [4][64][72]

  const int b = blockIdx.y;
  const int n0 = blockIdx.x * 32;
  const int tid = threadIdx.x;
  const int lane = tid & 31, wid = tid >> 5;
  const int gid = lane >> 2, tig = lane & 3;
  const int wn = (wid & 1) * 16;   // 2 n-warps
  const int wc = (wid >> 1) * 16;  // 4 c-warps

  const int lq = lane & 7;
  const int lsel = lane >> 3;
  const int a_row = lq + ((lsel & 2) ? 8 : 0);  // trans A (P^T): k row
  const int a_col = wn + ((lsel & 1) ? 8 : 0);  // n col
  const int b_row = lq + ((lsel & 1) ? 8 : 0);  // trans B (V): k row
  const int b_col = (lsel & 2) ? 8 : 0;         // c col

  const __nv_bfloat16* GP = g_P + (size_t)b * NN * NN;
  const __nv_bfloat16* Vb = g_Vsb + (size_t)b * NN * CC;

  float acc[2][4];
  #pragma unroll
  for (int j = 0; j < 2; j++)
    #pragma unroll
    for (int c = 0; c < 4; c++) acc[j][c] = 0.0f;

  #define ISSUE(bufe, mce)                                                      \
    {                                                                           \
      const int _buf = (bufe);                                                  \
      const int _mc = (mce);                                                    \
      {                                                                         \
        int rr = tid >> 2, ss = tid & 3;  /* 256 = 64 rows x 4 x 16B */         \
        cp16(&praw[(_buf * 64 + rr) * 40 + ss * 8],                             \
             GP + (size_t)(_mc + rr) * NN + n0 + ss * 8);                       \
      }                                                                         \
      _Pragma("unroll")                                                         \
      for (int ii = tid; ii < 512; ii += 256) {                                 \
        int rr = ii >> 3, ss = ii & 7;                                          \
        cp16(&vraw[(_buf * 64 + rr) * 72 + ss * 8],                             \
             Vb + (size_t)(_mc + rr) * 64 + ss * 8);                            \
      }                                                                         \
      asm volatile("cp.async.commit_group;" ::: "memory");                      \
    }

  ISSUE(0, 0);
  ISSUE(1, 64);
  ISSUE(2, 128);
  const int NCH = NN / 64;  // 64 chunks
  for (int i = 0; i < NCH; i++) {
    if (i + 3 < NCH) {
      ISSUE((i + 3) & 3, (i + 3) * 64);
      asm volatile("cp.async.wait_group 3;" ::: "memory");
    } else if (i + 2 < NCH) {
      asm volatile("cp.async.wait_group 2;" ::: "memory");
    } else if (i + 1 < NCH) {
      asm volatile("cp.async.wait_group 1;" ::: "memory");
    } else {
      asm volatile("cp.async.wait_group 0;" ::: "memory");
    }
    __syncthreads();

    const __nv_bfloat16* pb = &praw[(i & 3) * 64 * 40];
    const __nv_bfloat16* vb = &vraw[(i & 3) * 64 * 72];

    #pragma unroll
    for (int k0 = 0; k0 < 64; k0 += 16) {
      unsigned a0, a1, a2, a3;
      ldsm4t(a0, a1, a2, a3, &pb[(k0 + a_row) * 40 + a_col]);
      unsigned b0, b1, b2, b3;
      ldsm4t(b0, b1, b2, b3, &vb[(k0 + b_row) * 72 + wc + b_col]);
      mma_bf16(acc[0][0], acc[0][1], acc[0][2], acc[0][3], a0, a1, a2, a3, b0, b1);
      mma_bf16(acc[1][0], acc[1][1], acc[1][2], acc[1][3], a0, a1, a2, a3, b2, b3);
    }
    __syncthreads();
  }

  const float g = gamma[0];
  #pragma unroll
  for (int j = 0; j < 2; j++) {
    int c = wc + j * 8 + tig * 2;
    int n = n0 + wn + gid;
    size_t i0 = ((size_t)(b * NN) + n) * 64 + c;
    float2 xv = *(const float2*)&x[i0];
    float2 o;
    o.x = g * acc[j][0] + xv.x;
    o.y = g * acc[j][1] + xv.y;
    *(float2*)&out[i0] = o;
    size_t i1 = i0 + 8 * 64;  // n + 8
    float2 xv1 = *(const float2*)&x[i1];
    float2 o1;
    o1.x = g * acc[j][2] + xv1.x;
    o1.y = g * acc[j][3] + xv1.y;
    *(float2*)&out[i1] = o1;
  }
}

// ---------------------------------------------------------------------------
extern "C" void kernel_launch(void* const* d_in, const int* in_sizes, int n_in,
                              void* d_out, int out_size) {
  const float* x  = (const float*)d_in[0];
  const float* Wq = (const float*)d_in[1];
  const float* bq = (const float*)d_in[2];
  const float* Wk = (const float*)d_in[3];
  const float* bk = (const float*)d_in[4];
  const float* Wv = (const float*)d_in[5];
  const float* bv = (const float*)d_in[6];
  const float* gamma = (const float*)d_in[7];
  float* out = (float*)d_out;

  const int smemq = (64 * 65 + 3 * 64 * 65) * 4;         // 66560
  const int smem1 = 2 * 128 * 72 * 2 + 128 * 4;          // 37376
  const int smem2 = 4 * 64 * 40 * 2 + 4 * 64 * 72 * 2;   // 57344
  cudaFuncSetAttribute(qkv_kernel, cudaFuncAttributeMaxDynamicSharedMemorySize, smemq);
  cudaFuncSetAttribute(pass1_kernel, cudaFuncAttributeMaxDynamicSharedMemorySize, smem1);
  cudaFuncSetAttribute(pass2_kernel, cudaFuncAttributeMaxDynamicSharedMemorySize, smem2);

  qkv_kernel<<<(NB * NN) / 64, 256, smemq>>>(x, Wq, bq, Wk, bk, Wv, bv);
  pass1_kernel<<<dim3(NN / 128, NN / 128, NB), 256, smem1>>>();
  norm_kernel<<<(NB * NN) / 8, 256>>>();
  pass2_kernel<<<dim3(NN / 32, NB), 256, smem2>>>(x, gamma, out);
}

// round 11
// speedup vs baseline: 1.2065x; 1.2065x over previous
#include <cuda_runtime.h>
#include <cuda_bf16.h>
#include <cuda_fp16.h>
#include <math.h>

#define NB 4
#define NN 4096
#define CC 64
#define LOG2E 1.4426950408889634f
#define SHIFT2 (40.0f * LOG2E)

// Scratch (device globals — no allocation allowed)
__device__ __half g_Qh[NB * NN * CC];                // fp16 Q * log2(e)
__device__ __half g_Kh[NB * NN * CC];                // fp16 K
__device__ float g_V[NB * NN * CC];                  // full fp32
__device__ __nv_bfloat16 g_Vsb[NB * NN * CC];        // bf16(V * R)
__device__ __nv_bfloat16 g_P[(size_t)NB * NN * NN];  // unnormalized 2^(E' - SHIFT2)
__device__ float g_Sp[NB * 32 * NN];                 // partial row sums per n-tile

// ---------------------------------------------------------------------------
// helpers
// ---------------------------------------------------------------------------
__device__ __forceinline__ float ex2(float x) {
  float y;
  asm("ex2.approx.f32 %0, %1;" : "=f"(y) : "f"(x));
  return y;
}

__device__ __forceinline__ void mma_fp16(float& c0, float& c1, float& c2, float& c3,
                                         unsigned a0, unsigned a1, unsigned a2, unsigned a3,
                                         unsigned b0, unsigned b1) {
  asm volatile(
      "mma.sync.aligned.m16n8k16.row.col.f32.f16.f16.f32 "
      "{%0,%1,%2,%3},{%4,%5,%6,%7},{%8,%9},{%0,%1,%2,%3};"
      : "+f"(c0), "+f"(c1), "+f"(c2), "+f"(c3)
      : "r"(a0), "r"(a1), "r"(a2), "r"(a3), "r"(b0), "r"(b1));
}

__device__ __forceinline__ void mma_bf16(float& c0, float& c1, float& c2, float& c3,
                                         unsigned a0, unsigned a1, unsigned a2, unsigned a3,
                                         unsigned b0, unsigned b1) {
  asm volatile(
      "mma.sync.aligned.m16n8k16.row.col.f32.bf16.bf16.f32 "
      "{%0,%1,%2,%3},{%4,%5,%6,%7},{%8,%9},{%0,%1,%2,%3};"
      : "+f"(c0), "+f"(c1), "+f"(c2), "+f"(c3)
      : "r"(a0), "r"(a1), "r"(a2), "r"(a3), "r"(b0), "r"(b1));
}

__device__ __forceinline__ void ldsm4(unsigned& r0, unsigned& r1, unsigned& r2,
                                      unsigned& r3, const void* p) {
  unsigned addr = (unsigned)__cvta_generic_to_shared(p);
  asm volatile(
      "ldmatrix.sync.aligned.m8n8.x4.shared.b16 {%0,%1,%2,%3}, [%4];"
      : "=r"(r0), "=r"(r1), "=r"(r2), "=r"(r3)
      : "r"(addr));
}

__device__ __forceinline__ void ldsm4t(unsigned& r0, unsigned& r1, unsigned& r2,
                                       unsigned& r3, const void* p) {
  unsigned addr = (unsigned)__cvta_generic_to_shared(p);
  asm volatile(
      "ldmatrix.sync.aligned.m8n8.x4.trans.shared.b16 {%0,%1,%2,%3}, [%4];"
      : "=r"(r0), "=r"(r1), "=r"(r2), "=r"(r3)
      : "r"(addr));
}

__device__ __forceinline__ void cp16(void* smem_dst, const void* gsrc) {
  unsigned dst = (unsigned)__cvta_generic_to_shared(smem_dst);
  asm volatile("cp.async.cg.shared.global [%0], [%1], 16;" ::"r"(dst), "l"(gsrc)
               : "memory");
}

// ---------------------------------------------------------------------------
// Kernel 1: fused Q/K/V projection, W in smem. 64 rows/block.
// Q scaled by log2(e) so pass1 can use raw ex2.
// ---------------------------------------------------------------------------
__global__ __launch_bounds__(256) void qkv_kernel(
    const float* __restrict__ x,
    const float* __restrict__ Wq, const float* __restrict__ bq,
    const float* __restrict__ Wk, const float* __restrict__ bk,
    const float* __restrict__ Wv, const float* __restrict__ bv) {
  extern __shared__ float qsm[];
  float* xs = qsm;            // [64][65]
  float* ws = qsm + 64 * 65;  // [3][64][65]

  const int tid = threadIdx.x;
  const int row0 = blockIdx.x * 64;

  #pragma unroll
  for (int i = tid; i < 64 * 64; i += 256) {
    int r = i >> 6, c = i & 63;
    xs[r * 65 + c] = x[(size_t)(row0 + r) * 64 + c];
  }
  #pragma unroll
  for (int i = tid; i < 3 * 64 * 64; i += 256) {
    int mat = i >> 12, rem = i & 4095;
    int c = rem >> 6, f = rem & 63;
    const float* W = (mat == 0) ? Wq : (mat == 1) ? Wk : Wv;
    ws[(mat * 64 + c) * 65 + f] = W[c * 64 + f];
  }
  __syncthreads();

  const int lane = tid & 31;
  const int w = tid >> 5;
  const int f0 = lane, f1 = lane + 32;

  float aq[2][8], ak[2][8], av[2][8];
  {
    float bq0 = bq[f0], bq1 = bq[f1];
    float bk0 = bk[f0], bk1 = bk[f1];
    float bv0 = bv[f0], bv1 = bv[f1];
    #pragma unroll
    for (int i = 0; i < 8; i++) {
      aq[0][i] = bq0; aq[1][i] = bq1;
      ak[0][i] = bk0; ak[1][i] = bk1;
      av[0][i] = bv0; av[1][i] = bv1;
    }
  }

  #pragma unroll 4
  for (int c = 0; c < 64; c++) {
    float wq0 = ws[(0 * 64 + c) * 65 + f0], wq1 = ws[(0 * 64 + c) * 65 + f1];
    float wk0 = ws[(1 * 64 + c) * 65 + f0], wk1 = ws[(1 * 64 + c) * 65 + f1];
    float wv0 = ws[(2 * 64 + c) * 65 + f0], wv1 = ws[(2 * 64 + c) * 65 + f1];
    #pragma unroll
    for (int i = 0; i < 8; i++) {
      float xv = xs[(w * 8 + i) * 65 + c];
      aq[0][i] += xv * wq0; aq[1][i] += xv * wq1;
      ak[0][i] += xv * wk0; ak[1][i] += xv * wk1;
      av[0][i] += xv * wv0; av[1][i] += xv * wv1;
    }
  }

  #pragma unroll
  for (int i = 0; i < 8; i++) {
    size_t base = (size_t)(row0 + w * 8 + i) * 64;
    g_Qh[base + f0] = __float2half_rn(aq[0][i] * LOG2E);
    g_Qh[base + f1] = __float2half_rn(aq[1][i] * LOG2E);
    g_Kh[base + f0] = __float2half_rn(ak[0][i]);
    g_Kh[base + f1] = __float2half_rn(ak[1][i]);
    g_V[base + f0] = av[0][i];
    g_V[base + f1] = av[1][i];
  }
}

// ---------------------------------------------------------------------------
// Pass 1: E' tile (128m x 128n) via fp16 m16n8k16 MMA + ldmatrix;
// P = 2^(E' - SHIFT2) -> bf16 to HBM (uint4 stores); row partial sums -> g_Sp.
// ---------------------------------------------------------------------------
__global__ __launch_bounds__(256, 2) void pass1_kernel() {
  extern __shared__ char sm1[];
  __half* qh = (__half*)sm1;                       // [128][72]
  __half* kh = (__half*)(sm1 + 128 * 72 * 2);      // [128][72]
  float* ssum = (float*)(sm1 + 2 * 128 * 72 * 2);  // [128]
  __nv_bfloat162* ps2 = (__nv_bfloat162*)sm1;      // overlay [128][68]

  const int b = blockIdx.z;
  const int m0 = blockIdx.y * 128;
  const int n0 = blockIdx.x * 128;
  const int tid = threadIdx.x;
  const __half* Qb = g_Qh + (size_t)b * NN * CC;
  const __half* Kb = g_Kh + (size_t)b * NN * CC;

  #pragma unroll
  for (int i = tid; i < 1024; i += 256) {
    int r = i >> 3, s = i & 7;
    cp16(&qh[r * 72 + s * 8], Qb + (size_t)(m0 + r) * 64 + s * 8);
    cp16(&kh[r * 72 + s * 8], Kb + (size_t)(n0 + r) * 64 + s * 8);
  }
  asm volatile("cp.async.commit_group;" ::: "memory");
  if (tid < 128) ssum[tid] = 0.0f;
  asm volatile("cp.async.wait_group 0;" ::: "memory");
  __syncthreads();

  const int lane = tid & 31;
  const int wid = tid >> 5;
  const int gid = lane >> 2, tig = lane & 3;
  const int mw = (wid >> 1) * 32;
  const int nw = (wid & 1) * 64;

  const int lq = lane & 7;
  const int lsel = lane >> 3;
  const int row_off = lq + ((lsel & 1) ? 8 : 0);
  const int col_off = (lsel & 2) ? 8 : 0;

  float acc[2][8][4];
  #pragma unroll
  for (int t = 0; t < 2; t++)
    #pragma unroll
    for (int j = 0; j < 8; j++)
      #pragma unroll
      for (int c = 0; c < 4; c++) acc[t][j][c] = 0.0f;

  #pragma unroll
  for (int k0 = 0; k0 < 64; k0 += 16) {
    unsigned a[2][4];
    #pragma unroll
    for (int t = 0; t < 2; t++)
      ldsm4(a[t][0], a[t][1], a[t][2], a[t][3],
            &qh[(mw + t * 16 + row_off) * 72 + k0 + col_off]);

    unsigned bf[8][2];
    #pragma unroll
    for (int j2 = 0; j2 < 4; j2++) {
      unsigned r0, r1, r2, r3;
      ldsm4(r0, r1, r2, r3, &kh[(nw + j2 * 16 + row_off) * 72 + k0 + col_off]);
      bf[2 * j2][0] = r0; bf[2 * j2 + 1][0] = r1;
      bf[2 * j2][1] = r2; bf[2 * j2 + 1][1] = r3;
    }

    #pragma unroll
    for (int t = 0; t < 2; t++)
      #pragma unroll
      for (int j = 0; j < 8; j++)
        mma_fp16(acc[t][j][0], acc[t][j][1], acc[t][j][2], acc[t][j][3],
                 a[t][0], a[t][1], a[t][2], a[t][3], bf[j][0], bf[j][1]);
  }

  __syncthreads();  // tile reads done; safe to overlay ps2

  #pragma unroll
  for (int t = 0; t < 2; t++) {
    float s0 = 0.0f, s1 = 0.0f;
    int r0 = mw + t * 16 + gid;
    #pragma unroll
    for (int j = 0; j < 8; j++) {
      float e0 = ex2(acc[t][j][0] - SHIFT2);
      float e1 = ex2(acc[t][j][1] - SHIFT2);
      float e2 = ex2(acc[t][j][2] - SHIFT2);
      float e3 = ex2(acc[t][j][3] - SHIFT2);
      s0 += e0 + e1;
      s1 += e2 + e3;
      int cp = (nw >> 1) + j * 4 + tig;
      ps2[r0 * 68 + cp] = __floats2bfloat162_rn(e0, e1);
      ps2[(r0 + 8) * 68 + cp] = __floats2bfloat162_rn(e2, e3);
    }
    s0 += __shfl_xor_sync(0xffffffffu, s0, 1);
    s0 += __shfl_xor_sync(0xffffffffu, s0, 2);
    s1 += __shfl_xor_sync(0xffffffffu, s1, 1);
    s1 += __shfl_xor_sync(0xffffffffu, s1, 2);
    if (tig == 0) {
      atomicAdd(&ssum[r0], s0);
      atomicAdd(&ssum[r0 + 8], s1);
    }
  }
  __syncthreads();

  if (tid < 128)
    g_Sp[((size_t)b * 32 + blockIdx.x) * NN + m0 + tid] = ssum[tid];

  // drain P tile with 16B stores: 128 rows x 16 uint4 (row base 272B, 16B aligned)
  uint4* GP4 = (uint4*)(g_P + (size_t)b * NN * NN);
  #pragma unroll
  for (int i = tid; i < 2048; i += 256) {
    int r = i >> 4, s = i & 15;
    GP4[(size_t)(m0 + r) * (NN / 8) + (n0 >> 3) + s] =
        *(const uint4*)&ps2[r * 68 + s * 4];
  }
}

// ---------------------------------------------------------------------------
// norm: fused rsum + vscale (bf16 out). One warp per row.
// ---------------------------------------------------------------------------
__global__ __launch_bounds__(256) void norm_kernel() {
  const int row = blockIdx.x * 8 + (threadIdx.x >> 5);  // < NB*NN
  const int lane = threadIdx.x & 31;
  const int b = row >> 12, m = row & (NN - 1);

  float s = g_Sp[((size_t)b * 32 + lane) * NN + m];
  #pragma unroll
  for (int off = 16; off; off >>= 1) s += __shfl_xor_sync(0xffffffffu, s, off);
  const float rinv = 1.0f / s;

  size_t base = (size_t)row * 64;
  float v0 = g_V[base + 2 * lane], v1 = g_V[base + 2 * lane + 1];
  *(__nv_bfloat162*)&g_Vsb[base + 2 * lane] =
      __floats2bfloat162_rn(v0 * rinv, v1 * rinv);
}

// ---------------------------------------------------------------------------
// Pass 2: out[n,c] = gamma * sum_m P[m,n]*Vsb[m,c] + x[n,c]
// R8 tile config (64n x 64c, 3 buffers), single __syncthreads per chunk:
//   wait -> sync -> issue(i+2) -> compute.
// ---------------------------------------------------------------------------
__global__ __launch_bounds__(256, 2) void pass2_kernel(
    const float* __restrict__ x, const float* __restrict__ gamma,
    float* __restrict__ out) {
  extern __shared__ char sm[];
  __nv_bfloat16* praw = (__nv_bfloat16*)sm;                      // [3][64][72]
  __nv_bfloat16* vraw = (__nv_bfloat16*)(sm + 3 * 64 * 72 * 2);  // [3][64][72]

  const int b = blockIdx.y;
  const int n0 = blockIdx.x * 64;
  const int tid = threadIdx.x;
  const int lane = tid & 31, wid = tid >> 5;
  const int gid = lane >> 2, tig = lane & 3;
  const int wn = (wid & 3) * 16;
  const int wc = (wid >> 2) * 32;

  const int lq = lane & 7;
  const int lsel = lane >> 3;
  const int a_row = lq + ((lsel & 2) ? 8 : 0);
  const int a_col = wn + ((lsel & 1) ? 8 : 0);
  const int b_row = lq + ((lsel & 1) ? 8 : 0);
  const int b_col = (lsel & 2) ? 8 : 0;

  const __nv_bfloat16* GP = g_P + (size_t)b * NN * NN;
  const __nv_bfloat16* Vb = g_Vsb + (size_t)b * NN * CC;

  float acc[4][4];
  #pragma unroll
  for (int j = 0; j < 4; j++)
    #pragma unroll
    for (int c = 0; c < 4; c++) acc[j][c] = 0.0f;

  #define ISSUE(bufe, mce)                                                      \
    {                                                                           \
      const int _buf = (bufe);                                                  \
      const int _mc = (mce);                                                    \
      _Pragma("unroll")                                                         \
      for (int ii = tid; ii < 512; ii += 256) {                                 \
        int rr = ii >> 3, ss = ii & 7;                                          \
        cp16(&praw[(_buf * 64 + rr) * 72 + ss * 8],                             \
             GP + (size_t)(_mc + rr) * NN + n0 + ss * 8);                       \
      }                                                                         \
      _Pragma("unroll")                                                         \
      for (int ii = tid; ii < 512; ii += 256) {                                 \
        int rr = ii >> 3, ss = ii & 7;                                          \
        cp16(&vraw[(_buf * 64 + rr) * 72 + ss * 8],                             \
             Vb + (size_t)(_mc + rr) * 64 + ss * 8);                            \
      }                                                                         \
      asm volatile("cp.async.commit_group;" ::: "memory");                      \
    }

  ISSUE(0, 0);
  ISSUE(1, 64);
  const int NCH = NN / 64;  // 64 chunks
  for (int i = 0; i < NCH; i++) {
    if (i + 1 < NCH) {
      asm volatile("cp.async.wait_group 1;" ::: "memory");
    } else {
      asm volatile("cp.async.wait_group 0;" ::: "memory");
    }
    __syncthreads();  // chunk i visible to all; all warps done with iter i-1

    if (i + 2 < NCH) ISSUE((i + 2) % 3, (i + 2) * 64);

    const __nv_bfloat16* pb = &praw[(i % 3) * 64 * 72];
    const __nv_bfloat16* vb = &vraw[(i % 3) * 64 * 72];

    #pragma unroll
    for (int k0 = 0; k0 < 64; k0 += 16) {
      unsigned a0, a1, a2, a3;
      ldsm4t(a0, a1, a2, a3, &pb[(k0 + a_row) * 72 + a_col]);
      unsigned b00, b01, b02, b03, b10, b11, b12, b13;
      ldsm4t(b00, b01, b02, b03, &vb[(k0 + b_row) * 72 + wc + b_col]);
      ldsm4t(b10, b11, b12, b13, &vb[(k0 + b_row) * 72 + wc + 16 + b_col]);
      mma_bf16(acc[0][0], acc[0][1], acc[0][2], acc[0][3], a0, a1, a2, a3, b00, b01);
      mma_bf16(acc[1][0], acc[1][1], acc[1][2], acc[1][3], a0, a1, a2, a3, b02, b03);
      mma_bf16(acc[2][0], acc[2][1], acc[2][2], acc[2][3], a0, a1, a2, a3, b10, b11);
      mma_bf16(acc[3][0], acc[3][1], acc[3][2], acc[3][3], a0, a1, a2, a3, b12, b13);
    }
  }

  const float g = gamma[0];
  #pragma unroll
  for (int j = 0; j < 4; j++) {
    int c = wc + j * 8 + tig * 2;
    int n = n0 + wn + gid;
    size_t i0 = ((size_t)(b * NN) + n) * 64 + c;
    float2 xv = *(const float2*)&x[i0];
    float2 o;
    o.x = g * acc[j][0] + xv.x;
    o.y = g * acc[j][1] + xv.y;
    *(float2*)&out[i0] = o;
    size_t i1 = i0 + 8 * 64;
    float2 xv1 = *(const float2*)&x[i1];
    float2 o1;
    o1.x = g * acc[j][2] + xv1.x;
    o1.y = g * acc[j][3] + xv1.y;
    *(float2*)&out[i1] = o1;
  }
}

// ---------------------------------------------------------------------------
extern "C" void kernel_launch(void* const* d_in, const int* in_sizes, int n_in,
                              void* d_out, int out_size) {
  const float* x  = (const float*)d_in[0];
  const float* Wq = (const float*)d_in[1];
  const float* bq = (const float*)d_in[2];
  const float* Wk = (const float*)d_in[3];
  const float* bk = (const float*)d_in[4];
  const float* Wv = (const float*)d_in[5];
  const float* bv = (const float*)d_in[6];
  const float* gamma = (const float*)d_in[7];
  float* out = (float*)d_out;

  const int smemq = (64 * 65 + 3 * 64 * 65) * 4;  // 66560
  const int smem1 = 2 * 128 * 72 * 2 + 128 * 4;   // 37376
  const int smem2 = 2 * 3 * 64 * 72 * 2;          // 55296
  cudaFuncSetAttribute(qkv_kernel, cudaFuncAttributeMaxDynamicSharedMemorySize, smemq);
  cudaFuncSetAttribute(pass1_kernel, cudaFuncAttributeMaxDynamicSharedMemorySize, smem1);
  cudaFuncSetAttribute(pass2_kernel, cudaFuncAttributeMaxDynamicSharedMemorySize, smem2);

  qkv_kernel<<<(NB * NN) / 64, 256, smemq>>>(x, Wq, bq, Wk, bk, Wv, bv);
  pass1_kernel<<<dim3(NN / 128, NN / 128, NB), 256, smem1>>>();
  norm_kernel<<<(NB * NN) / 8, 256>>>();
  pass2_kernel<<<dim3(NN / 64, NB), 256, smem2>>>(x, gamma, out);
}